// round 15
// baseline (speedup 1.0000x reference)
#include <cuda_runtime.h>
#include <cuda_bf16.h>
#include <cstdint>

#define DF   64
#define DC   256
#define HF   240
#define WF   320
#define HW   (HF*WF)
#define LC   4800
#define WW   25
#define NMAX 16384
#define BST  72        // main B bf16 row stride (144B, conflict-free ldmatrix)
#define WFST 264       // coarse WfT bf16 row stride (528B, conflict-free ldsm)
#define CVST 260       // coarse cv f32 smem stride (1040B, conflict-free LDS.64)
#define STROW 272      // output staging row stride (bytes)

typedef unsigned long long u64;
typedef unsigned int u32;
typedef unsigned short u16;

__device__ float g_biasf[DF];
__device__ float g_cc[2 * NMAX * DF];
__device__ u16   g_Bhi[DF * BST];
__device__ u16   g_Blo[DF * BST];
__device__ u16   g_WfT_hi[DF * WFST];
__device__ u16   g_WfT_lo[DF * WFST];
__device__ int   g_ctr;

// ================= helpers =================
__device__ __forceinline__ u32 smem_u32(const void* p) {
    u32 a; asm("{ .reg .u64 t; cvta.to.shared.u64 t, %1; cvt.u32.u64 %0, t; }" : "=r"(a) : "l"(p));
    return a;
}
__device__ __forceinline__ void ldsm_x4(u32* r, u32 addr) {
    asm volatile("ldmatrix.sync.aligned.m8n8.x4.shared.b16 {%0,%1,%2,%3}, [%4];"
                 : "=r"(r[0]), "=r"(r[1]), "=r"(r[2]), "=r"(r[3]) : "r"(addr));
}
__device__ __forceinline__ void mma_bf16(float* d, const u32* a, const u32* b) {
    asm volatile("mma.sync.aligned.m16n8k16.row.col.f32.bf16.bf16.f32 "
                 "{%0,%1,%2,%3}, {%4,%5,%6,%7}, {%8,%9}, {%0,%1,%2,%3};"
                 : "+f"(d[0]), "+f"(d[1]), "+f"(d[2]), "+f"(d[3])
                 : "r"(a[0]), "r"(a[1]), "r"(a[2]), "r"(a[3]), "r"(b[0]), "r"(b[1]));
}
__device__ __forceinline__ u32 packbf(float hi, float lo) {
    u32 d; asm("cvt.rn.bf16x2.f32 %0, %1, %2;" : "=r"(d) : "f"(hi), "f"(lo)); return d;
}

#define CP16(dst, src) asm volatile("cp.async.cg.shared.global [%0], [%1], 16;" :: "r"(dst), "l"(src))
#define CP_COMMIT()    asm volatile("cp.async.commit_group;")
#define CP_WAIT0()     asm volatile("cp.async.wait_group 0;" ::: "memory")
#define CP_WAIT1()     asm volatile("cp.async.wait_group 1;" ::: "memory")

// ================= weight prep (split-k, 128 threads) + counter reset =================
__global__ __launch_bounds__(128) void prep_weights_kernel(
    const float* __restrict__ Wd, const float* __restrict__ Wm,
    const float* __restrict__ bd, const float* __restrict__ bm,
    int initCtr)
{
    __shared__ float red[2][DF];
    int bi = blockIdx.x;
    int j = threadIdx.x & 63;
    int h = threadIdx.x >> 6;
    if (bi == 0 && threadIdx.x == 0) g_ctr = initCtr;
    if (bi < DC) {
        float acc = 0.f;
        int k0 = h * 32;
#pragma unroll
        for (int k = 0; k < 32; k++)
            acc += Wd[bi * DF + k0 + k] * Wm[(DF + k0 + k) * DF + j];
        red[h][j] = acc;
        __syncthreads();
        if (h == 0) {
            float a = red[0][j] + red[1][j];
            __nv_bfloat16 hh = __float2bfloat16(a);
            float lo = a - __bfloat162float(hh);
            __nv_bfloat16 ll = __float2bfloat16(lo);
            g_WfT_hi[j * WFST + bi] = *(u16*)&hh;
            g_WfT_lo[j * WFST + bi] = *(u16*)&ll;
            if (bi == 0) {
                float b = bm[j];
#pragma unroll
                for (int k = 0; k < DF; k++)
                    b += bd[k] * Wm[(DF + k) * DF + j];
                g_biasf[j] = b;
            }
        }
    } else if (h == 0) {
        int n = bi - DC;
        int k = j;
        float v = Wm[k * DF + n];
        __nv_bfloat16 hh = __float2bfloat16(v);
        float lo = v - __bfloat162float(hh);
        __nv_bfloat16 ll = __float2bfloat16(lo);
        g_Bhi[n * BST + k] = *(u16*)&hh;
        g_Blo[n * BST + k] = *(u16*)&ll;
    }
}

// ================= coarse projection: MMA, persistent, double-buffered =================
#define CO_WFH  0
#define CO_WFL  33792
#define CO_CV0  67584
#define CO_CV1  134144
#define CO_SMEM 200704

__global__ __launch_bounds__(256) void coarse_mma_kernel(
    const float* __restrict__ c0, const float* __restrict__ c1,
    const int* __restrict__ b_ids, const int* __restrict__ ci, int N)
{
    extern __shared__ char csm[];
    const u32 csb = smem_u32(csm);
    __shared__ const float* s_ptr[2][64];
    __shared__ int s_off[2][64];

    const int tid = threadIdx.x;
    const int total = 2 * N;
    const int nB = (total + 63) >> 6;
    const int stride = gridDim.x;

    auto stageOff = [&](int batch, int bufI) {
        if (tid < 64) {
            int item = batch * 64 + tid;
            if (item >= total) item = total - 1;
            int s = item >= N;
            int p = item - s * N;
            s_ptr[bufI][tid] = s ? c1 : c0;
            s_off[bufI][tid] = (__ldg(b_ids + p) * LC + __ldg(ci + p)) * DC;
        }
    };
    auto stageCv = [&](int bufI) {
        u32 base = csb + (bufI ? CO_CV1 : CO_CV0);
        for (int c = tid; c < 64 * 64; c += 256) {
            int it = c >> 6, k16 = c & 63;
            const float* src = s_ptr[bufI][it] + s_off[bufI][it] + k16 * 4;
            CP16(base + (u32)(it * CVST * 4 + k16 * 16), src);
        }
    };

    if (blockIdx.x >= nB) return;

    stageOff(blockIdx.x, 0);
    __syncthreads();
    {
        const char* sH = (const char*)g_WfT_hi;
        const char* sL = (const char*)g_WfT_lo;
        for (int i = tid * 16; i < DF * WFST * 2; i += 256 * 16) {
            CP16(csb + CO_WFH + i, sH + i);
            CP16(csb + CO_WFL + i, sL + i);
        }
        stageCv(0);
    }
    CP_COMMIT();

    const int lane = tid & 31;
    const int wid = tid >> 5;
    const int mt = wid >> 1;
    const int nh = wid & 1;
    const int r  = lane >> 2;
    const int kq = (lane & 3) * 2;
    const u32 bRow = (u32)((((lane >> 4) & 1) * 8 + (lane & 7)) * (WFST * 2));
    const u32 bCol = (u32)(((lane >> 3) & 1) * 16);

    int buf = 0;
    for (int cur = blockIdx.x; cur < nB; cur += stride) {
        int nxt = cur + stride;
        if (nxt < nB) {
            stageOff(nxt, buf ^ 1);
            __syncthreads();
            stageCv(buf ^ 1);
            CP_COMMIT();
            CP_WAIT1();
        } else {
            CP_WAIT0();
        }
        __syncthreads();

        const float* cv = (const float*)(csm + (buf ? CO_CV1 : CO_CV0));

        float acc[4][4];
#pragma unroll
        for (int nt = 0; nt < 4; nt++)
#pragma unroll
            for (int q = 0; q < 4; q++) acc[nt][q] = 0.f;

#pragma unroll 4
        for (int kt = 0; kt < 16; kt++) {
            int k0 = kt * 16 + kq;
            const float* rowA = cv + (mt * 16 + r) * CVST;
            const float* rowB = rowA + 8 * CVST;
            float2 f0 = *(const float2*)(rowA + k0);
            float2 f1 = *(const float2*)(rowB + k0);
            float2 f2 = *(const float2*)(rowA + k0 + 8);
            float2 f3 = *(const float2*)(rowB + k0 + 8);

            u32 ah[4], al[4];
            {
                u32 h;
                h = packbf(f0.y, f0.x); ah[0] = h;
                al[0] = packbf(f0.y - __uint_as_float(h & 0xffff0000u),
                               f0.x - __uint_as_float(h << 16));
                h = packbf(f1.y, f1.x); ah[1] = h;
                al[1] = packbf(f1.y - __uint_as_float(h & 0xffff0000u),
                               f1.x - __uint_as_float(h << 16));
                h = packbf(f2.y, f2.x); ah[2] = h;
                al[2] = packbf(f2.y - __uint_as_float(h & 0xffff0000u),
                               f2.x - __uint_as_float(h << 16));
                h = packbf(f3.y, f3.x); ah[3] = h;
                al[3] = packbf(f3.y - __uint_as_float(h & 0xffff0000u),
                               f3.x - __uint_as_float(h << 16));
            }

            u32 bh[2][4], bl[2][4];
#pragma unroll
            for (int ntp = 0; ntp < 2; ntp++) {
                u32 rowBase = (u32)((nh * 2 + ntp) * 16 * (WFST * 2));
                u32 baddr = rowBase + bRow + (u32)(kt * 32) + bCol;
                ldsm_x4(bh[ntp], csb + CO_WFH + baddr);
                ldsm_x4(bl[ntp], csb + CO_WFL + baddr);
            }
#pragma unroll
            for (int ntp = 0; ntp < 2; ntp++)
#pragma unroll
                for (int sub = 0; sub < 2; sub++) {
                    int nt = ntp * 2 + sub;
                    u32 bhp[2] = {bh[ntp][sub * 2], bh[ntp][sub * 2 + 1]};
                    u32 blp[2] = {bl[ntp][sub * 2], bl[ntp][sub * 2 + 1]};
                    mma_bf16(acc[nt], ah, bhp);
                    mma_bf16(acc[nt], ah, blp);
                    mma_bf16(acc[nt], al, bhp);
                }
        }

        {
            int base = cur * 64;
            int it0 = base + mt * 16 + r;
            int it1 = it0 + 8;
#pragma unroll
            for (int nt = 0; nt < 4; nt++) {
                int c = (nh * 4 + nt) * 8 + kq;
                float2 bias = *(const float2*)(g_biasf + c);
                if (it0 < total)
                    *(float2*)(g_cc + (size_t)it0 * DF + c) =
                        make_float2(acc[nt][0] + bias.x, acc[nt][1] + bias.y);
                if (it1 < total)
                    *(float2*)(g_cc + (size_t)it1 * DF + c) =
                        make_float2(acc[nt][2] + bias.x, acc[nt][3] + bias.y);
            }
        }
        __syncthreads();
        buf ^= 1;
    }
}

// ================= main kernel: work steal + cc/index prefetch + coalesced stores =================
#define SMB_HI 0
#define SMB_LO 9216
#define SMB_STAGE 18432
#define STG_WARP (WW * STROW)          // 6800 B per warp

__global__ __launch_bounds__(128, 3) void fine_main_kernel(
    const float* __restrict__ f0, const float* __restrict__ f1,
    const int* __restrict__ b_ids, const int* __restrict__ cy,
    const int* __restrict__ cx,
    float* __restrict__ out, int N)
{
    __shared__ __align__(16) char smem[SMB_STAGE + 4 * STG_WARP];   // 45632
    const u32 sb = smem_u32(smem);
    const int tid = threadIdx.x;
    const int wid = tid >> 5;
    const int lane = tid & 31;
    const int total = 2 * N;

    // ---- stage B (once per block) ----
    {
        const char* srcH = (const char*)g_Bhi;
        const char* srcL = (const char*)g_Blo;
        for (int i = tid * 16; i < DF * BST * 2; i += 128 * 16) {
            CP16(sb + SMB_HI + i, srcH + i);
            CP16(sb + SMB_LO + i, srcL + i);
        }
    }
    CP_COMMIT();
    CP_WAIT0();
    __syncthreads();

    const int g = lane >> 2;            // row phase 0..7
    const int c2 = (lane & 3) * 2;      // ch pair base
    const int jc = (lane & 3) * 2;

    int woffp[4];
#pragma unroll
    for (int pi = 0; pi < 4; pi++) {
        int p = g + 8 * pi;
        if (p >= WW) p -= 8;
        int dy = p / 5;
        woffp[pi] = dy * WF + (p - dy * 5);
    }

    const u32 bRow = (u32)((((lane >> 4) & 1) * 8 + (lane & 7)) * (BST * 2));
    const u32 bCol = (u32)(((lane >> 3) & 1) * 16);
    char* stw = smem + SMB_STAGE + wid * STG_WARP;

    // per-warp work stealing with index prefetch
    int item = blockIdx.x * 4 + wid;
    int curB = 0, curY = 0, curX = 0;
    if (item < total) {
        int s = item >= N;
        int p = item - s * N;
        curB = __ldg(b_ids + p); curY = __ldg(cy + p); curX = __ldg(cx + p);
    }

    while (item < total) {
        // grab next item + prefetch ITS indices — both hide behind this item's work
        int nextItem;
        if (lane == 0) nextItem = atomicAdd(&g_ctr, 1);
        nextItem = __shfl_sync(0xffffffffu, nextItem, 0);
        int nxtB, nxtY, nxtX;
        {
            int ni = nextItem < total ? nextItem : item;
            int s2 = ni >= N;
            int p2 = ni - s2 * N;
            nxtB = __ldg(b_ids + p2); nxtY = __ldg(cy + p2); nxtX = __ldg(cx + p2);
        }

        int s = item >= N;
        const float* fsrc = s ? f1 : f0;
        const float* fbase = fsrc + (size_t)curB * (DF * HW)
                           + (size_t)(curY - 2) * WF + (curX - 2);

        const float* bp[4];
#pragma unroll
        for (int pi = 0; pi < 4; pi++) bp[pi] = fbase + woffp[pi];

        // ---- batched gather: 64 LDG.32 into regs ----
        float va[64];
#pragma unroll
        for (int kt = 0; kt < 4; kt++)
#pragma unroll
            for (int pi = 0; pi < 4; pi++)
#pragma unroll
                for (int jh = 0; jh < 2; jh++)
#pragma unroll
                    for (int e = 0; e < 2; e++) {
                        int ch = kt * 16 + c2 + jh * 8 + e;
                        va[kt * 16 + pi * 4 + jh * 2 + e] =
                            __ldg(bp[pi] + (size_t)ch * HW);
                    }

        // ---- prefetch coarse vector (hides behind gather) ----
        float2 ccv[8];
        {
            const float* ccb = g_cc + (size_t)item * DF + jc;
#pragma unroll
            for (int ntg = 0; ntg < 8; ntg++)
                ccv[ntg] = *(const float2*)(ccb + ntg * 8);
        }

        // ---- in-register bf16 hi/lo fragment build ----
        u32 ah[4][2][4], al[4][2][4];
#pragma unroll
        for (int kt = 0; kt < 4; kt++)
#pragma unroll
            for (int mt = 0; mt < 2; mt++)
#pragma unroll
                for (int j = 0; j < 4; j++) {
                    int pi = mt * 2 + (j & 1), jh = j >> 1;
                    float v0 = va[kt * 16 + pi * 4 + jh * 2 + 0];
                    float v1 = va[kt * 16 + pi * 4 + jh * 2 + 1];
                    u32 h = packbf(v1, v0);
                    float h0 = __uint_as_float(h << 16);
                    float h1 = __uint_as_float(h & 0xffff0000u);
                    ah[kt][mt][j] = h;
                    al[kt][mt][j] = packbf(v1 - h1, v0 - h0);
                }

#pragma unroll
        for (int nh = 0; nh < 2; nh++) {
            float acc[2][4][4];
#pragma unroll
            for (int mt = 0; mt < 2; mt++)
#pragma unroll
                for (int nt = 0; nt < 4; nt++)
#pragma unroll
                    for (int q = 0; q < 4; q++) acc[mt][nt][q] = 0.f;

#pragma unroll
            for (int kt = 0; kt < 4; kt++) {
                u32 bh[2][4], bl[2][4];
#pragma unroll
                for (int ntp = 0; ntp < 2; ntp++) {
                    u32 rowBase = (u32)((nh * 2 + ntp) * 16 * (BST * 2));
                    u32 baddr = rowBase + bRow + (u32)(kt * 32) + bCol;
                    ldsm_x4(bh[ntp], sb + SMB_HI + baddr);
                    ldsm_x4(bl[ntp], sb + SMB_LO + baddr);
                }
#pragma unroll
                for (int ntp = 0; ntp < 2; ntp++)
#pragma unroll
                    for (int sub = 0; sub < 2; sub++) {
                        int nt = ntp * 2 + sub;
                        u32 bhp[2] = {bh[ntp][sub * 2], bh[ntp][sub * 2 + 1]};
                        u32 blp[2] = {bl[ntp][sub * 2], bl[ntp][sub * 2 + 1]};
#pragma unroll
                        for (int mt = 0; mt < 2; mt++) {
                            mma_bf16(acc[mt][nt], ah[kt][mt], bhp);
                            mma_bf16(acc[mt][nt], ah[kt][mt], blp);
                            mma_bf16(acc[mt][nt], al[kt][mt], bhp);
                        }
                    }
            }

            // ---- stage (acc + cc) into per-warp smem tile ----
#pragma unroll
            for (int nt = 0; nt < 4; nt++) {
                int ntg = nh * 4 + nt;
                float2 cc = ccv[ntg];
                int cb = (ntg * 8 + jc) * 4;
#pragma unroll
                for (int mt = 0; mt < 2; mt++) {
                    int r0 = mt * 16 + g;
                    *(float2*)(stw + r0 * STROW + cb) =
                        make_float2(acc[mt][nt][0] + cc.x, acc[mt][nt][1] + cc.y);
                    if (mt == 0 || g == 0) {
                        int r1 = r0 + 8;
                        *(float2*)(stw + r1 * STROW + cb) =
                            make_float2(acc[mt][nt][2] + cc.x, acc[mt][nt][3] + cc.y);
                    }
                }
            }
        }

        // ---- coalesced store: 2 rows per STG.128 pass ----
        __syncwarp();
        {
            float* ob = out + (size_t)item * (WW * DF);
            const int half = lane >> 4;       // 0/1 -> row parity
            const int cq = (lane & 15) * 4;   // 4-float column chunk
#pragma unroll
            for (int rr = 0; rr < 13; rr++) {
                int row = rr * 2 + half;
                if (row < WW) {
                    float4 v = *(const float4*)(stw + row * STROW + cq * 4);
                    *(float4*)(ob + row * DF + cq) = v;
                }
            }
        }
        __syncwarp();

        item = nextItem;
        curB = nxtB; curY = nxtY; curX = nxtX;
    }
}

extern "C" void kernel_launch(void* const* d_in, const int* in_sizes, int n_in,
                              void* d_out, int out_size) {
    const float* f0    = (const float*)d_in[0];
    const float* f1    = (const float*)d_in[1];
    const float* c0    = (const float*)d_in[2];
    const float* c1    = (const float*)d_in[3];
    const float* Wd    = (const float*)d_in[4];
    const float* bd    = (const float*)d_in[5];
    const float* Wm    = (const float*)d_in[6];
    const float* bm    = (const float*)d_in[7];
    const int*   b_ids = (const int*)d_in[8];
    const int*   cy    = (const int*)d_in[9];
    const int*   cx    = (const int*)d_in[10];
    const int*   ci    = (const int*)d_in[11];
    float* out = (float*)d_out;

    int N = in_sizes[8];
    int total = 2 * N;

    int nGroups = (total + 3) / 4;
    int mblocks = 3 * 152;
    if (mblocks > nGroups) mblocks = nGroups;

    prep_weights_kernel<<<DC + DF, 128>>>(Wd, Wm, bd, bm, mblocks * 4);

    static int attr_set = 0;
    if (!attr_set) {
        cudaFuncSetAttribute(coarse_mma_kernel,
                             cudaFuncAttributeMaxDynamicSharedMemorySize, CO_SMEM);
        attr_set = 1;
    }

    int nB = (total + 63) / 64;
    int cblocks = nB < 152 ? nB : 152;
    coarse_mma_kernel<<<cblocks, 256, CO_SMEM>>>(c0, c1, b_ids, ci, N);

    fine_main_kernel<<<mblocks, 128>>>(f0, f1, b_ids, cy, cx, out, N);
}

// round 16
// speedup vs baseline: 1.0339x; 1.0339x over previous
#include <cuda_runtime.h>
#include <cuda_bf16.h>
#include <cstdint>

#define DF   64
#define DC   256
#define HF   240
#define WF   320
#define HW   (HF*WF)
#define LC   4800
#define WW   25
#define NMAX 16384
#define BST  72        // main B bf16 row stride (144B, conflict-free ldmatrix)
#define WFST 264       // coarse WfT bf16 row stride (528B, conflict-free ldsm)
#define CVST 260       // coarse cv f32 smem stride (1040B, conflict-free LDS.64)

typedef unsigned long long u64;
typedef unsigned int u32;
typedef unsigned short u16;

__device__ float g_biasf[DF];
__device__ float g_cc[2 * NMAX * DF];
__device__ u16   g_Bhi[DF * BST];
__device__ u16   g_Blo[DF * BST];
__device__ u16   g_WfT_hi[DF * WFST];
__device__ u16   g_WfT_lo[DF * WFST];
__device__ int   g_ctr;

// ================= helpers =================
__device__ __forceinline__ u32 smem_u32(const void* p) {
    u32 a; asm("{ .reg .u64 t; cvta.to.shared.u64 t, %1; cvt.u32.u64 %0, t; }" : "=r"(a) : "l"(p));
    return a;
}
__device__ __forceinline__ void ldsm_x4(u32* r, u32 addr) {
    asm volatile("ldmatrix.sync.aligned.m8n8.x4.shared.b16 {%0,%1,%2,%3}, [%4];"
                 : "=r"(r[0]), "=r"(r[1]), "=r"(r[2]), "=r"(r[3]) : "r"(addr));
}
__device__ __forceinline__ void mma_bf16(float* d, const u32* a, const u32* b) {
    asm volatile("mma.sync.aligned.m16n8k16.row.col.f32.bf16.bf16.f32 "
                 "{%0,%1,%2,%3}, {%4,%5,%6,%7}, {%8,%9}, {%0,%1,%2,%3};"
                 : "+f"(d[0]), "+f"(d[1]), "+f"(d[2]), "+f"(d[3])
                 : "r"(a[0]), "r"(a[1]), "r"(a[2]), "r"(a[3]), "r"(b[0]), "r"(b[1]));
}
__device__ __forceinline__ u32 packbf(float hi, float lo) {
    u32 d; asm("cvt.rn.bf16x2.f32 %0, %1, %2;" : "=r"(d) : "f"(hi), "f"(lo)); return d;
}

#define CP16(dst, src) asm volatile("cp.async.cg.shared.global [%0], [%1], 16;" :: "r"(dst), "l"(src))
#define CP_COMMIT()    asm volatile("cp.async.commit_group;")
#define CP_WAIT0()     asm volatile("cp.async.wait_group 0;" ::: "memory")
#define CP_WAIT1()     asm volatile("cp.async.wait_group 1;" ::: "memory")

// ================= weight prep (split-k, 128 threads) + counter reset =================
__global__ __launch_bounds__(128) void prep_weights_kernel(
    const float* __restrict__ Wd, const float* __restrict__ Wm,
    const float* __restrict__ bd, const float* __restrict__ bm,
    int initCtr)
{
    __shared__ float red[2][DF];
    int bi = blockIdx.x;
    int j = threadIdx.x & 63;
    int h = threadIdx.x >> 6;
    if (bi == 0 && threadIdx.x == 0) g_ctr = initCtr;
    if (bi < DC) {
        float acc = 0.f;
        int k0 = h * 32;
#pragma unroll
        for (int k = 0; k < 32; k++)
            acc += Wd[bi * DF + k0 + k] * Wm[(DF + k0 + k) * DF + j];
        red[h][j] = acc;
        __syncthreads();
        if (h == 0) {
            float a = red[0][j] + red[1][j];
            __nv_bfloat16 hh = __float2bfloat16(a);
            float lo = a - __bfloat162float(hh);
            __nv_bfloat16 ll = __float2bfloat16(lo);
            g_WfT_hi[j * WFST + bi] = *(u16*)&hh;
            g_WfT_lo[j * WFST + bi] = *(u16*)&ll;
            if (bi == 0) {
                float b = bm[j];
#pragma unroll
                for (int k = 0; k < DF; k++)
                    b += bd[k] * Wm[(DF + k) * DF + j];
                g_biasf[j] = b;
            }
        }
    } else if (h == 0) {
        int n = bi - DC;
        int k = j;
        float v = Wm[k * DF + n];
        __nv_bfloat16 hh = __float2bfloat16(v);
        float lo = v - __bfloat162float(hh);
        __nv_bfloat16 ll = __float2bfloat16(lo);
        g_Bhi[n * BST + k] = *(u16*)&hh;
        g_Blo[n * BST + k] = *(u16*)&ll;
    }
}

// ================= coarse projection: MMA, persistent, double-buffered =================
#define CO_WFH  0
#define CO_WFL  33792
#define CO_CV0  67584
#define CO_CV1  134144
#define CO_SMEM 200704

__global__ __launch_bounds__(256) void coarse_mma_kernel(
    const float* __restrict__ c0, const float* __restrict__ c1,
    const int* __restrict__ b_ids, const int* __restrict__ ci, int N)
{
    extern __shared__ char csm[];
    const u32 csb = smem_u32(csm);
    __shared__ const float* s_ptr[2][64];
    __shared__ int s_off[2][64];

    const int tid = threadIdx.x;
    const int total = 2 * N;
    const int nB = (total + 63) >> 6;
    const int stride = gridDim.x;

    auto stageOff = [&](int batch, int bufI) {
        if (tid < 64) {
            int item = batch * 64 + tid;
            if (item >= total) item = total - 1;
            int s = item >= N;
            int p = item - s * N;
            s_ptr[bufI][tid] = s ? c1 : c0;
            s_off[bufI][tid] = (__ldg(b_ids + p) * LC + __ldg(ci + p)) * DC;
        }
    };
    auto stageCv = [&](int bufI) {
        u32 base = csb + (bufI ? CO_CV1 : CO_CV0);
        for (int c = tid; c < 64 * 64; c += 256) {
            int it = c >> 6, k16 = c & 63;
            const float* src = s_ptr[bufI][it] + s_off[bufI][it] + k16 * 4;
            CP16(base + (u32)(it * CVST * 4 + k16 * 16), src);
        }
    };

    if (blockIdx.x >= nB) return;

    stageOff(blockIdx.x, 0);
    __syncthreads();
    {
        const char* sH = (const char*)g_WfT_hi;
        const char* sL = (const char*)g_WfT_lo;
        for (int i = tid * 16; i < DF * WFST * 2; i += 256 * 16) {
            CP16(csb + CO_WFH + i, sH + i);
            CP16(csb + CO_WFL + i, sL + i);
        }
        stageCv(0);
    }
    CP_COMMIT();

    const int lane = tid & 31;
    const int wid = tid >> 5;
    const int mt = wid >> 1;
    const int nh = wid & 1;
    const int r  = lane >> 2;
    const int kq = (lane & 3) * 2;
    const u32 bRow = (u32)((((lane >> 4) & 1) * 8 + (lane & 7)) * (WFST * 2));
    const u32 bCol = (u32)(((lane >> 3) & 1) * 16);

    int buf = 0;
    for (int cur = blockIdx.x; cur < nB; cur += stride) {
        int nxt = cur + stride;
        if (nxt < nB) {
            stageOff(nxt, buf ^ 1);
            __syncthreads();
            stageCv(buf ^ 1);
            CP_COMMIT();
            CP_WAIT1();
        } else {
            CP_WAIT0();
        }
        __syncthreads();

        const float* cv = (const float*)(csm + (buf ? CO_CV1 : CO_CV0));

        float acc[4][4];
#pragma unroll
        for (int nt = 0; nt < 4; nt++)
#pragma unroll
            for (int q = 0; q < 4; q++) acc[nt][q] = 0.f;

#pragma unroll 4
        for (int kt = 0; kt < 16; kt++) {
            int k0 = kt * 16 + kq;
            const float* rowA = cv + (mt * 16 + r) * CVST;
            const float* rowB = rowA + 8 * CVST;
            float2 f0 = *(const float2*)(rowA + k0);
            float2 f1 = *(const float2*)(rowB + k0);
            float2 f2 = *(const float2*)(rowA + k0 + 8);
            float2 f3 = *(const float2*)(rowB + k0 + 8);

            u32 ah[4], al[4];
            {
                u32 h;
                h = packbf(f0.y, f0.x); ah[0] = h;
                al[0] = packbf(f0.y - __uint_as_float(h & 0xffff0000u),
                               f0.x - __uint_as_float(h << 16));
                h = packbf(f1.y, f1.x); ah[1] = h;
                al[1] = packbf(f1.y - __uint_as_float(h & 0xffff0000u),
                               f1.x - __uint_as_float(h << 16));
                h = packbf(f2.y, f2.x); ah[2] = h;
                al[2] = packbf(f2.y - __uint_as_float(h & 0xffff0000u),
                               f2.x - __uint_as_float(h << 16));
                h = packbf(f3.y, f3.x); ah[3] = h;
                al[3] = packbf(f3.y - __uint_as_float(h & 0xffff0000u),
                               f3.x - __uint_as_float(h << 16));
            }

            u32 bh[2][4], bl[2][4];
#pragma unroll
            for (int ntp = 0; ntp < 2; ntp++) {
                u32 rowBase = (u32)((nh * 2 + ntp) * 16 * (WFST * 2));
                u32 baddr = rowBase + bRow + (u32)(kt * 32) + bCol;
                ldsm_x4(bh[ntp], csb + CO_WFH + baddr);
                ldsm_x4(bl[ntp], csb + CO_WFL + baddr);
            }
#pragma unroll
            for (int ntp = 0; ntp < 2; ntp++)
#pragma unroll
                for (int sub = 0; sub < 2; sub++) {
                    int nt = ntp * 2 + sub;
                    u32 bhp[2] = {bh[ntp][sub * 2], bh[ntp][sub * 2 + 1]};
                    u32 blp[2] = {bl[ntp][sub * 2], bl[ntp][sub * 2 + 1]};
                    mma_bf16(acc[nt], ah, bhp);
                    mma_bf16(acc[nt], ah, blp);
                    mma_bf16(acc[nt], al, bhp);
                }
        }

        {
            int base = cur * 64;
            int it0 = base + mt * 16 + r;
            int it1 = it0 + 8;
#pragma unroll
            for (int nt = 0; nt < 4; nt++) {
                int c = (nh * 4 + nt) * 8 + kq;
                float2 bias = *(const float2*)(g_biasf + c);
                if (it0 < total)
                    *(float2*)(g_cc + (size_t)it0 * DF + c) =
                        make_float2(acc[nt][0] + bias.x, acc[nt][1] + bias.y);
                if (it1 < total)
                    *(float2*)(g_cc + (size_t)it1 * DF + c) =
                        make_float2(acc[nt][2] + bias.x, acc[nt][3] + bias.y);
            }
        }
        __syncthreads();
        buf ^= 1;
    }
}

// ================= main kernel: work steal + cc prefetch + index prefetch =================
#define SMB_HI 0
#define SMB_LO 9216

__global__ __launch_bounds__(128, 3) void fine_main_kernel(
    const float* __restrict__ f0, const float* __restrict__ f1,
    const int* __restrict__ b_ids, const int* __restrict__ cy,
    const int* __restrict__ cx,
    float* __restrict__ out, int N)
{
    __shared__ __align__(16) char smem[DF * BST * 2 * 2];   // 18432
    const u32 sb = smem_u32(smem);
    const int tid = threadIdx.x;
    const int wid = tid >> 5;
    const int lane = tid & 31;
    const int total = 2 * N;

    // ---- stage B (once per block) ----
    {
        const char* srcH = (const char*)g_Bhi;
        const char* srcL = (const char*)g_Blo;
        for (int i = tid * 16; i < DF * BST * 2; i += 128 * 16) {
            CP16(sb + SMB_HI + i, srcH + i);
            CP16(sb + SMB_LO + i, srcL + i);
        }
    }
    CP_COMMIT();
    CP_WAIT0();
    __syncthreads();

    const int g = lane >> 2;            // row phase 0..7
    const int c2 = (lane & 3) * 2;      // ch pair base
    const int jc = (lane & 3) * 2;

    int woffp[4];
#pragma unroll
    for (int pi = 0; pi < 4; pi++) {
        int p = g + 8 * pi;
        if (p >= WW) p -= 8;
        int dy = p / 5;
        woffp[pi] = dy * WF + (p - dy * 5);
    }

    const u32 bRow = (u32)((((lane >> 4) & 1) * 8 + (lane & 7)) * (BST * 2));
    const u32 bCol = (u32)(((lane >> 3) & 1) * 16);

    // per-warp work stealing with index prefetch
    int item = blockIdx.x * 4 + wid;
    int curB = 0, curY = 0, curX = 0;
    if (item < total) {
        int s = item >= N;
        int p = item - s * N;
        curB = __ldg(b_ids + p); curY = __ldg(cy + p); curX = __ldg(cx + p);
    }

    while (item < total) {
        // grab next item + prefetch ITS indices — both hide behind this item's work
        int nextItem;
        if (lane == 0) nextItem = atomicAdd(&g_ctr, 1);
        nextItem = __shfl_sync(0xffffffffu, nextItem, 0);
        int nxtB, nxtY, nxtX;
        {
            int ni = nextItem < total ? nextItem : item;
            int s2 = ni >= N;
            int p2 = ni - s2 * N;
            nxtB = __ldg(b_ids + p2); nxtY = __ldg(cy + p2); nxtX = __ldg(cx + p2);
        }

        int s = item >= N;
        const float* fsrc = s ? f1 : f0;
        const float* fbase = fsrc + (size_t)curB * (DF * HW)
                           + (size_t)(curY - 2) * WF + (curX - 2);

        const float* bp[4];
#pragma unroll
        for (int pi = 0; pi < 4; pi++) bp[pi] = fbase + woffp[pi];

        // ---- batched gather: 64 LDG.32 into regs ----
        float va[64];
#pragma unroll
        for (int kt = 0; kt < 4; kt++)
#pragma unroll
            for (int pi = 0; pi < 4; pi++)
#pragma unroll
                for (int jh = 0; jh < 2; jh++)
#pragma unroll
                    for (int e = 0; e < 2; e++) {
                        int ch = kt * 16 + c2 + jh * 8 + e;
                        va[kt * 16 + pi * 4 + jh * 2 + e] =
                            __ldg(bp[pi] + (size_t)ch * HW);
                    }

        // ---- prefetch coarse vector (hides behind gather) ----
        float2 ccv[8];
        {
            const float* ccb = g_cc + (size_t)item * DF + jc;
#pragma unroll
            for (int ntg = 0; ntg < 8; ntg++)
                ccv[ntg] = *(const float2*)(ccb + ntg * 8);
        }

        // ---- in-register bf16 hi/lo fragment build ----
        u32 ah[4][2][4], al[4][2][4];
#pragma unroll
        for (int kt = 0; kt < 4; kt++)
#pragma unroll
            for (int mt = 0; mt < 2; mt++)
#pragma unroll
                for (int j = 0; j < 4; j++) {
                    int pi = mt * 2 + (j & 1), jh = j >> 1;
                    float v0 = va[kt * 16 + pi * 4 + jh * 2 + 0];
                    float v1 = va[kt * 16 + pi * 4 + jh * 2 + 1];
                    u32 h = packbf(v1, v0);
                    float h0 = __uint_as_float(h << 16);
                    float h1 = __uint_as_float(h & 0xffff0000u);
                    ah[kt][mt][j] = h;
                    al[kt][mt][j] = packbf(v1 - h1, v0 - h0);
                }

        float* ob = out + (size_t)item * (WW * DF) + jc;

#pragma unroll
        for (int nh = 0; nh < 2; nh++) {
            float acc[2][4][4];
#pragma unroll
            for (int mt = 0; mt < 2; mt++)
#pragma unroll
                for (int nt = 0; nt < 4; nt++)
#pragma unroll
                    for (int q = 0; q < 4; q++) acc[mt][nt][q] = 0.f;

#pragma unroll
            for (int kt = 0; kt < 4; kt++) {
                u32 bh[2][4], bl[2][4];
#pragma unroll
                for (int ntp = 0; ntp < 2; ntp++) {
                    u32 rowBase = (u32)((nh * 2 + ntp) * 16 * (BST * 2));
                    u32 baddr = rowBase + bRow + (u32)(kt * 32) + bCol;
                    ldsm_x4(bh[ntp], sb + SMB_HI + baddr);
                    ldsm_x4(bl[ntp], sb + SMB_LO + baddr);
                }
#pragma unroll
                for (int ntp = 0; ntp < 2; ntp++)
#pragma unroll
                    for (int sub = 0; sub < 2; sub++) {
                        int nt = ntp * 2 + sub;
                        u32 bhp[2] = {bh[ntp][sub * 2], bh[ntp][sub * 2 + 1]};
                        u32 blp[2] = {bl[ntp][sub * 2], bl[ntp][sub * 2 + 1]};
#pragma unroll
                        for (int mt = 0; mt < 2; mt++) {
                            mma_bf16(acc[mt][nt], ah[kt][mt], bhp);
                            mma_bf16(acc[mt][nt], ah[kt][mt], blp);
                            mma_bf16(acc[mt][nt], al[kt][mt], bhp);
                        }
                    }
            }

#pragma unroll
            for (int nt = 0; nt < 4; nt++) {
                int ntg = nh * 4 + nt;
                float2 cc = ccv[ntg];
#pragma unroll
                for (int mt = 0; mt < 2; mt++) {
                    int r0 = mt * 16 + g;
                    *(float2*)(ob + r0 * DF + ntg * 8) =
                        make_float2(acc[mt][nt][0] + cc.x, acc[mt][nt][1] + cc.y);
                    if (mt == 0 || g == 0) {
                        int r1 = r0 + 8;
                        *(float2*)(ob + r1 * DF + ntg * 8) =
                            make_float2(acc[mt][nt][2] + cc.x, acc[mt][nt][3] + cc.y);
                    }
                }
            }
        }

        item = nextItem;
        curB = nxtB; curY = nxtY; curX = nxtX;
    }
}

extern "C" void kernel_launch(void* const* d_in, const int* in_sizes, int n_in,
                              void* d_out, int out_size) {
    const float* f0    = (const float*)d_in[0];
    const float* f1    = (const float*)d_in[1];
    const float* c0    = (const float*)d_in[2];
    const float* c1    = (const float*)d_in[3];
    const float* Wd    = (const float*)d_in[4];
    const float* bd    = (const float*)d_in[5];
    const float* Wm    = (const float*)d_in[6];
    const float* bm    = (const float*)d_in[7];
    const int*   b_ids = (const int*)d_in[8];
    const int*   cy    = (const int*)d_in[9];
    const int*   cx    = (const int*)d_in[10];
    const int*   ci    = (const int*)d_in[11];
    float* out = (float*)d_out;

    int N = in_sizes[8];
    int total = 2 * N;

    int nGroups = (total + 3) / 4;
    int mblocks = 3 * 152;
    if (mblocks > nGroups) mblocks = nGroups;

    prep_weights_kernel<<<DC + DF, 128>>>(Wd, Wm, bd, bm, mblocks * 4);

    static int attr_set = 0;
    if (!attr_set) {
        cudaFuncSetAttribute(coarse_mma_kernel,
                             cudaFuncAttributeMaxDynamicSharedMemorySize, CO_SMEM);
        attr_set = 1;
    }

    int nB = (total + 63) / 64;
    int cblocks = nB < 152 ? nB : 152;
    coarse_mma_kernel<<<cblocks, 256, CO_SMEM>>>(c0, c1, b_ids, ci, N);

    fine_main_kernel<<<mblocks, 128>>>(f0, f1, b_ids, cy, cx, out, N);
}